// round 15
// baseline (speedup 1.0000x reference)
#include <cuda_runtime.h>
#include <cuda_fp16.h>
#include <cstdint>

// ============================================================================
// Portable PTX helpers (mma.sync / ldmatrix / cp.async only — no 'a'-gated ops)
// ============================================================================

__device__ __forceinline__ uint32_t smem_to_u32(const void* smem_ptr) {
    uint32_t addr;
    asm("{ .reg .u64 tmp; cvta.to.shared.u64 tmp, %1; cvt.u32.u64 %0, tmp; }"
        : "=r"(addr) : "l"(smem_ptr));
    return addr;
}

__device__ __forceinline__ void cp_async16(uint32_t dst, const void* src) {
    asm volatile("cp.async.cg.shared.global [%0], [%1], 16;"
                 :: "r"(dst), "l"(__cvta_generic_to_global(src)));
}
__device__ __forceinline__ void cp_commit() {
    asm volatile("cp.async.commit_group;" ::: "memory");
}
__device__ __forceinline__ void cp_wait0() {
    asm volatile("cp.async.wait_group 0;" ::: "memory");
}

__device__ __forceinline__ void ldmx4(uint32_t* r, uint32_t addr) {
    asm volatile("ldmatrix.sync.aligned.m8n8.x4.shared.b16 {%0,%1,%2,%3}, [%4];"
                 : "=r"(r[0]), "=r"(r[1]), "=r"(r[2]), "=r"(r[3]) : "r"(addr));
}

__device__ __forceinline__ void mma16816(float* c, const uint32_t* a, const uint32_t* b) {
    asm volatile(
        "mma.sync.aligned.m16n8k16.row.col.f32.f16.f16.f32 "
        "{%0,%1,%2,%3}, {%4,%5,%6,%7}, {%8,%9}, {%0,%1,%2,%3};"
        : "+f"(c[0]), "+f"(c[1]), "+f"(c[2]), "+f"(c[3])
        : "r"(a[0]), "r"(a[1]), "r"(a[2]), "r"(a[3]), "r"(b[0]), "r"(b[1]));
}

// packed fp32x2 -> fp16x2 convert (round-to-nearest, identical to __float2half_rn)
__device__ __forceinline__ uint32_t cvt2h(float lo, float hi) {
    uint32_t r;
    asm("cvt.rn.f16x2.f32 %0, %1, %2;" : "=r"(r) : "f"(hi), "f"(lo));
    return r;
}

// evict-first vector store (output is write-once, keep it out of L2)
__device__ __forceinline__ void stg_cs2(float* p, float a, float b) {
    asm volatile("st.global.cs.v2.f32 [%0], {%1, %2};"
                 :: "l"(__cvta_generic_to_global(p)), "f"(a), "f"(b) : "memory");
}

// named barrier: 4 warps of one row group (128 threads)
__device__ __forceinline__ void group_bar(int id) {
    asm volatile("bar.sync %0, %1;" :: "r"(id), "r"(128) : "memory");
}

// ============================================================================
// Problem constants
// ============================================================================
static constexpr int DIN = 256;    // K
static constexpr int BM  = 128;    // CTA M tile
static constexpr int BN  = 256;    // CTA N tile
static constexpr int BK  = 64;     // K chunk (4 k16 steps)
static constexpr int NCHUNK = DIN / BK;  // 4

static constexpr int A_STRIDE = 144;   // 64 fp16 (128B) + 16B pad -> conflict-free
static constexpr int B_STRIDE = 528;   // 256 fp16 (512B) + 16B pad -> conflict-free
static constexpr int A_STAGE  = BM * A_STRIDE;   // 18432

// smem layout (dynamic, bytes)
static constexpr int SM_B    = 0;                   // 256 * 528 = 135168 (persistent)
static constexpr int SM_A    = 135168;              // 2 stages * 18432 = 36864
static constexpr int SM_BIAS = 172032;              // 256 floats = 1024
static constexpr int SMEM_SZ = 173056;

// ============================================================================
// Device scratch (no allocation allowed -> __device__ globals)
// ============================================================================
__device__ float  g_bias[512];           // [0:256) combined bias c1, [256:512) out bias c2
__device__ __half g_Bh[512 * 256];       // fused weight, [n][k] row-major, fp16

// ============================================================================
// Single prep kernel (measured-good, unchanged)
// ============================================================================

__device__ __forceinline__ float warp_sum(float v) {
#pragma unroll
    for (int o = 16; o > 0; o >>= 1) v += __shfl_xor_sync(0xffffffffu, v, o);
    return v;
}

__device__ __forceinline__ float gate_of(const float* pre, const float* post,
                                         int k, int lane) {
    float a = pre[k * 256 + lane];
    float b = post[k * 32 + lane];
    float sp = warp_sum(a * a);
    float sq = warp_sum(b * b);
    float np = fmaxf(sqrtf(sp), 1e-12f);
    float nq = fmaxf(sqrtf(sq), 1e-12f);
    float d  = warp_sum((a / np) * (b / nq));
    float align = 1.0f / (1.0f + expf(-d));
    return (align >= 0.3f) ? align : 0.0f;
}

__global__ void __launch_bounds__(128, 8)
prep_all(const float* __restrict__ Wc, const float* __restrict__ Wp,
         const float* __restrict__ bp,
         const float* __restrict__ pre, const float* __restrict__ post,
         const float* __restrict__ Wo, const float* __restrict__ bo,
         float* __restrict__ out_tail) {
    __shared__ float sW[4][256];
    __shared__ float sU[4][256];
    __shared__ float sGate[8];
    const int bid = blockIdx.x;
    const bool isW2 = bid >= 128;
    const int rg  = (bid & 127) >> 1;
    const int h   = bid & 1;
    const int tid = threadIdx.x;
    const int col = h * 128 + tid;
    const int o0  = rg * 4;
    const int w   = tid >> 5, lane = tid & 31;

    if (!isW2) {
        const int ko = o0 >> 5;
        if (tid < 32) {
            float g = gate_of(pre, post, ko, lane);
            if (lane == 0) {
                sGate[0] = g;
                if ((rg & 7) == 0 && h == 0) {
                    out_tail[ko] = g;          // alignments
                    out_tail[8 + ko] = 1.0f;   // allocation_mask
                }
            }
        }
        __syncthreads();
        const float g = sGate[0];
#pragma unroll
        for (int r = 0; r < 4; ++r) {
            sW[r][tid]       = Wc[(o0 + r) * 256 + tid] * g;
            sW[r][128 + tid] = Wc[(o0 + r) * 256 + 128 + tid] * g;
        }
        __syncthreads();

        float acc[4] = {0.f, 0.f, 0.f, 0.f};
#pragma unroll 16
        for (int i = 0; i < 256; ++i) {
            float wv = Wp[i * 256 + col];
#pragma unroll
            for (int r = 0; r < 4; ++r) acc[r] += sW[r][i] * wv;
        }
#pragma unroll
        for (int r = 0; r < 4; ++r)
            g_Bh[(o0 + r) * 256 + col] = __float2half_rn(acc[r]);

        if (h == 0) {
            float p = 0.f;
#pragma unroll
            for (int k = 0; k < 8; ++k)
                p += sW[w][lane + 32 * k] * bp[lane + 32 * k];
            p = warp_sum(p);
            if (lane == 0) g_bias[o0 + w] = p;
        }
    } else {
#pragma unroll
        for (int kk = w; kk < 8; kk += 4) {
            float g = gate_of(pre, post, kk, lane);
            if (lane == 0) sGate[kk] = g;
        }
        __syncthreads();

#pragma unroll
        for (int r = 0; r < 4; ++r) {
            sW[r][tid]       = Wo[(o0 + r) * 256 + tid] * sGate[tid >> 5];
            sW[r][128 + tid] = Wo[(o0 + r) * 256 + 128 + tid] * sGate[(128 + tid) >> 5];
        }
        __syncthreads();

        float ua[4], ub[4];
#pragma unroll
        for (int r = 0; r < 4; ++r) { ua[r] = 0.f; ub[r] = 0.f; }
#pragma unroll 8
        for (int j = 0; j < 256; ++j) {
            float c0 = Wc[j * 256 + tid];
            float c1 = Wc[j * 256 + 128 + tid];
#pragma unroll
            for (int r = 0; r < 4; ++r) { ua[r] += sW[r][j] * c0; ub[r] += sW[r][j] * c1; }
        }
#pragma unroll
        for (int r = 0; r < 4; ++r) { sU[r][tid] = ua[r]; sU[r][128 + tid] = ub[r]; }
        __syncthreads();

        float acc[4] = {0.f, 0.f, 0.f, 0.f};
#pragma unroll 16
        for (int i = 0; i < 256; ++i) {
            float wv = Wp[i * 256 + col];
#pragma unroll
            for (int r = 0; r < 4; ++r) acc[r] += sU[r][i] * wv;
        }
#pragma unroll
        for (int r = 0; r < 4; ++r)
            g_Bh[(256 + o0 + r) * 256 + col] = __float2half_rn(acc[r]);

        if (h == 0) {
            float p = 0.f;
#pragma unroll
            for (int k = 0; k < 8; ++k)
                p += sU[w][lane + 32 * k] * bp[lane + 32 * k];
            p = warp_sum(p);
            if (lane == 0) g_bias[256 + o0 + w] = p + bo[o0 + w];
        }
    }
}

// ============================================================================
// Main fused GEMM: 8 warps, warp tile 64x64 (halves smem bytes per MMA vs
// 32x64). CTA tile 128x256, block 256, 1 CTA/SM. Persistent, nt-split grid,
// cross-tile prefetch, per-row-group (128-thread) named barriers, .cs stores.
// ============================================================================
__global__ void __launch_bounds__(256, 1)
fused_main(const float* __restrict__ x, float* __restrict__ out,
           int Brows, int ntiles) {
    extern __shared__ char smem[];
    const uint32_t sb = smem_to_u32(smem);
    const int tid  = threadIdx.x;
    const int wid  = tid >> 5, lane = tid & 31;
    const int wm   = wid >> 2;               // 2 row groups of 64 rows (warps 0-3 / 4-7)
    const int wn   = wid & 3;                // 4 col groups of 64 cols

    const int split  = (int)(gridDim.x >> 1);
    const int nt     = (blockIdx.x >= split) ? 1 : 0;
    const int cid    = nt ? ((int)blockIdx.x - split) : (int)blockIdx.x;
    const int stride = nt ? ((int)gridDim.x - split) : split;

    // ---- persistent B tile (256 rows x full K) + bias, loaded once ----
    {
        const __half* Bg = g_Bh + (size_t)nt * BN * DIN;
        const uint32_t bd = sb + SM_B;
#pragma unroll
        for (int i = 0; i < 32; ++i) {
            int idx = tid + 256 * i;            // 8192 x 16B
            int row = idx >> 5, kseg = idx & 31;
            cp_async16(bd + row * B_STRIDE + kseg * 16, Bg + row * DIN + kseg * 8);
        }
        if (tid < 64)
            cp_async16(sb + SM_BIAS + tid * 16, g_bias + nt * BN + tid * 4);
        cp_commit();
    }

    // A staging: 2 threads per row, each owns half a chunk-row (32 floats).
    // group wm covers rows [wm*64, wm*64+64) == tids [wm*128, wm*128+128).
    const int gtid  = tid & 127;
    const int prow  = wm * 64 + (gtid >> 1);     // row within CTA tile
    const int phalf = gtid & 1;                  // which 32-float half
    const size_t tile_step = (size_t)stride * BM * DIN;

    const int arow  = wm * 64 + (lane & 15);
    const uint32_t acolb = ((lane >> 4) & 1) * 16;
    const int brow0 = wn * 64 + ((lane & 7) | ((lane >> 4) << 3));
    const uint32_t bcolb = ((lane >> 3) & 1) * 16;
    const int barid = 1 + wm;

    // epilogue base: nt==0 -> combined block (second Brows*256); nt==1 -> out block
    float* hbase = out + (nt ? (size_t)0 : (size_t)Brows * 256);
    const float* bias_s = (const float*)(smem + SM_BIAS);

    // initial x prefetch (tile cid, chunk 0), then publish B once
    const float* xrow0 = x + (size_t)cid * BM * DIN + prow * DIN + phalf * 32;
    float4 pre[8];
    if (cid < ntiles) {
#pragma unroll
        for (int j = 0; j < 8; ++j)
            pre[j] = *(const float4*)(xrow0 + j * 4);
    }
    cp_wait0();
    __syncthreads();   // B + bias visible CTA-wide

    for (int mt = cid; mt < ntiles; mt += stride) {
        const float* xrow = x + (size_t)mt * BM * DIN + prow * DIN + phalf * 32;

        float acc[4][8][4];
#pragma unroll
        for (int m = 0; m < 4; m++)
#pragma unroll
            for (int n = 0; n < 8; n++)
#pragma unroll
                for (int k = 0; k < 4; k++) acc[m][n][k] = 0.f;

#pragma unroll 1
        for (int c = 0; c < NCHUNK; ++c) {
            const int s = c & 1;

            // ---- convert prefetched fp32 -> fp16 (packed cvt), STS stage s ----
            {
                char* As = smem + SM_A + s * A_STAGE + prow * A_STRIDE + phalf * 64;
#pragma unroll
                for (int j = 0; j < 4; ++j) {
                    uint4 hp;
                    hp.x = cvt2h(pre[2 * j].x,     pre[2 * j].y);
                    hp.y = cvt2h(pre[2 * j].z,     pre[2 * j].w);
                    hp.z = cvt2h(pre[2 * j + 1].x, pre[2 * j + 1].y);
                    hp.w = cvt2h(pre[2 * j + 1].z, pre[2 * j + 1].w);
                    *(uint4*)(As + j * 16) = hp;
                }
            }
            group_bar(barid);   // only the 4 warps of this 64-row group

            // ---- prefetch chunk c+1, or next tile's chunk 0 ----
            if (c + 1 < NCHUNK) {
#pragma unroll
                for (int j = 0; j < 8; ++j)
                    pre[j] = *(const float4*)(xrow + (c + 1) * BK + j * 4);
            } else if (mt + stride < ntiles) {
#pragma unroll
                for (int j = 0; j < 8; ++j)
                    pre[j] = *(const float4*)(xrow + tile_step + j * 4);
            }

            // ---- 4 k16 steps of MMA (64x64 warp tile: 8 ldmx4 -> 32 MMAs) ----
            const uint32_t abase = sb + SM_A + s * A_STAGE;
            const uint32_t bks   = sb + SM_B + (uint32_t)(c * 128);
#pragma unroll
            for (int ks = 0; ks < 4; ++ks) {
                uint32_t af[4][4], bf[4][4];
#pragma unroll
                for (int m = 0; m < 4; ++m)
                    ldmx4(af[m], abase + (uint32_t)((arow + m * 16) * A_STRIDE) + acolb + ks * 32);
#pragma unroll
                for (int p = 0; p < 4; ++p)
                    ldmx4(bf[p], bks + (uint32_t)((brow0 + p * 16) * B_STRIDE) + bcolb + ks * 32);
#pragma unroll
                for (int m = 0; m < 4; ++m)
#pragma unroll
                    for (int n = 0; n < 8; ++n)
                        mma16816(acc[m][n], af[m], &bf[n >> 1][(n & 1) * 2]);
            }
        }

        // ---- epilogue: add fused bias (smem), evict-first stores ----
#pragma unroll
        for (int m = 0; m < 4; ++m) {
            const int row = mt * BM + wm * 64 + m * 16 + (lane >> 2);
            float* rp = hbase + (size_t)row * 256;
#pragma unroll
            for (int n = 0; n < 8; ++n) {
                const int ln = wn * 64 + n * 8 + (lane & 3) * 2;   // 0..255 column
                const float b0 = bias_s[ln], b1 = bias_s[ln + 1];
                stg_cs2(rp + ln,           acc[m][n][0] + b0, acc[m][n][1] + b1);
                stg_cs2(rp + ln + 8 * 256, acc[m][n][2] + b0, acc[m][n][3] + b1);
            }
        }
    }
}

// ============================================================================
// kernel_launch
// ============================================================================
extern "C" void kernel_launch(void* const* d_in, const int* in_sizes, int n_in,
                              void* d_out, int out_size) {
    const float* x    = (const float*)d_in[0];
    const float* Wp   = (const float*)d_in[1];
    const float* bp   = (const float*)d_in[2];
    const float* pre  = (const float*)d_in[3];
    const float* post = (const float*)d_in[4];
    const float* Wc   = (const float*)d_in[5];
    const float* Wo   = (const float*)d_in[6];
    const float* bo   = (const float*)d_in[7];
    float* out = (float*)d_out;
    const int Brows  = in_sizes[0] / 256;     // 131072
    const int ntiles = Brows / BM;            // 1024

    cudaFuncSetAttribute(fused_main, cudaFuncAttributeMaxDynamicSharedMemorySize, SMEM_SZ);

    int dev = 0, sms = 148;
    cudaGetDevice(&dev);
    cudaDeviceGetAttribute(&sms, cudaDevAttrMultiProcessorCount, dev);
    int grid = sms & ~1;                      // even split across the two N-halves
    if (grid > 2 * ntiles) grid = 2 * ntiles;

    prep_all<<<256, 128>>>(Wc, Wp, bp, pre, post, Wo, bo,
                           out + (size_t)2 * Brows * 256);
    fused_main<<<grid, 256, SMEM_SZ>>>(x, out, Brows, ntiles);
}